// round 12
// baseline (speedup 1.0000x reference)
#include <cuda_runtime.h>
#include <cuda_bf16.h>
#include <cstdint>

#define BB 16
#define PP 96
#define TT 128
#define VV 64
#define NN 16
#define DD 128

// ---------------------------------------------------------------------------
// PTX helpers
// ---------------------------------------------------------------------------
__device__ __forceinline__ uint32_t smem_to_u32(const void* p) {
    uint32_t a;
    asm("{ .reg .u64 t; cvta.to.shared.u64 t, %1; cvt.u32.u64 %0, t; }"
        : "=r"(a) : "l"(p));
    return a;
}
__device__ __forceinline__ void ldsm4(uint32_t* r, uint32_t addr) {
    asm volatile("ldmatrix.sync.aligned.m8n8.x4.shared.b16 {%0,%1,%2,%3}, [%4];"
        : "=r"(r[0]), "=r"(r[1]), "=r"(r[2]), "=r"(r[3]) : "r"(addr));
}
__device__ __forceinline__ void mma_bf16(float* d, const uint32_t* a,
                                         const uint32_t* b) {
    asm volatile(
        "mma.sync.aligned.m16n8k16.row.col.f32.bf16.bf16.f32 "
        "{%0,%1,%2,%3}, {%4,%5,%6,%7}, {%8,%9}, {%0,%1,%2,%3};"
        : "+f"(d[0]), "+f"(d[1]), "+f"(d[2]), "+f"(d[3])
        : "r"(a[0]), "r"(a[1]), "r"(a[2]), "r"(a[3]), "r"(b[0]), "r"(b[1]));
}
#define CVT_BF2(w, xhi, xlo) \
    asm("cvt.rn.bf16x2.f32 %0, %1, %2;" : "=r"(w) : "f"(xhi), "f"(xlo))
#define CP_ASYNC16(dst, src) \
    asm volatile("cp.async.ca.shared.global [%0], [%1], 16;" :: "r"(dst), "l"(src))
#define CP_COMMIT() asm volatile("cp.async.commit_group;" ::: "memory")
#define CP_WAIT0()  asm volatile("cp.async.wait_group 0;" ::: "memory")

// split fp32 pair -> hi bf16x2 word + lo residual word (low half = x0)
__device__ __forceinline__ void split2(float x0, float x1, uint32_t& h, uint32_t& l) {
    CVT_BF2(h, x1, x0);
    float f0 = __uint_as_float(h << 16);
    float f1 = __uint_as_float(h & 0xFFFF0000u);
    CVT_BF2(l, x1 - f1, x0 - f0);
}

// ---------------------------------------------------------------------------
// Scratch
// ---------------------------------------------------------------------------
__device__ float g_q[BB*PP*VV*DD];        // projected queries fp32
__device__ float g_k[BB*TT*VV*DD];        // projected keys fp32 (t>=32 rows used)
__device__ uint32_t g_kbh[BB*TT*VV*64];   // projected keys hi bf16x2 (t<32 rows)
__device__ uint32_t g_kbl[BB*TT*VV*64];

// ---------------------------------------------------------------------------
// Split-bf16 warp-tile MMA over a 272B-stride A stage + resident W (hi at
// w_base, lo at w_base+34816). 16x32 warp tile at (warp_m, warp_n).
// ---------------------------------------------------------------------------
__device__ __forceinline__ void mma_tile(uint32_t a_base, int a_lo_off,
                                         uint32_t w_base, int lane,
                                         int warp_m, int warp_n, float acc[4][4]) {
    uint32_t a0 = a_base + (uint32_t)(warp_m * 16 + (lane & 15)) * 272
                + ((lane >> 4) * 16);
    int bj = warp_n * 32 + (lane & 7) + ((lane >> 4) * 8);
    uint32_t b0 = w_base + (uint32_t)bj * 272 + (((lane >> 3) & 1) * 16);
#pragma unroll
    for (int ks = 0; ks < 8; ks++) {
        uint32_t ah[4], al[4], bh[2][4], bl[2][4];
        ldsm4(ah, a0 + ks * 32);
        ldsm4(al, a0 + a_lo_off + ks * 32);
        ldsm4(bh[0], b0 + ks * 32);
        ldsm4(bh[1], b0 + 16 * 272 + ks * 32);
        ldsm4(bl[0], b0 + 34816 + ks * 32);
        ldsm4(bl[1], b0 + 34816 + 16 * 272 + ks * 32);
#pragma unroll
        for (int ni = 0; ni < 2; ni++)
#pragma unroll
            for (int s2 = 0; s2 < 2; s2++) {
                float* d = acc[2 * ni + s2];
                mma_bf16(d, ah, &bh[ni][2 * s2]);
                mma_bf16(d, ah, &bl[ni][2 * s2]);
                mma_bf16(d, al, &bh[ni][2 * s2]);
            }
    }
}

// ===========================================================================
// gemm_qk (round-6 form, measured 76.3us): persistent q/k projection.
// ===========================================================================
static constexpr int OFF_BHI  = 0;
static constexpr int OFF_BLO  = 34816;
static constexpr int OFF_A    = 69632;
static constexpr int STAGE_B  = 17408;
static constexpr int GEMM_SMEM = OFF_A + 2 * STAGE_B;   // 104448

static constexpr int NCTA = 296;
static constexpr int NQC  = 127;
static constexpr int NKC  = NCTA - NQC;   // 169
static constexpr int NQT  = BB*PP*VV/32;  // 3072
static constexpr int NKT  = BB*TT*VV/32;  // 4096

__device__ __forceinline__ void load_W256(char* smem, const float* __restrict__ W, int t) {
#pragma unroll
    for (int i = 0; i < 32; i++) {
        int e = t + 256 * i;
        int j = e >> 6, w = e & 63;
        float2 p = *(const float2*)(W + 2 * e);
        uint32_t h, l;
        split2(p.x, p.y, h, l);
        *(uint32_t*)(smem + OFF_BHI + j * 272 + w * 4) = h;
        *(uint32_t*)(smem + OFF_BLO + j * 272 + w * 4) = l;
    }
}

__global__ void __launch_bounds__(256, 2)
gemm_qk(const float* __restrict__ queries, const float* __restrict__ keys,
        const float* __restrict__ Wq, const float* __restrict__ Wkv,
        const float* __restrict__ bq, const float* __restrict__ bkv) {
    extern __shared__ char smem[];
    const uint32_t sbase = smem_to_u32(smem);
    int t = threadIdx.x, lane = t & 31, wid = t >> 5;
    int warp_m = wid >> 2, warp_n = wid & 3;
    int cta = blockIdx.x;
    bool isq = cta < NQC;
    int tile  = isq ? cta : cta - NQC;
    int tstep = isq ? NQC : NKC;
    int NT    = isq ? NQT : NKT;
    const float* X    = isq ? queries : keys;
    const float* bias = isq ? bq : bkv;

    load_W256(smem, isq ? Wq : Wkv, t);

    int ocol0 = warp_n * 32 + 2 * (lane & 3);
    float2 bv[4];
#pragma unroll
    for (int nf = 0; nf < 4; nf++) bv[nf] = *(const float2*)(bias + ocol0 + nf * 8);

    float4 ap[4];
#pragma unroll
    for (int i = 0; i < 4; i++)
        ap[i] = ((const float4*)(X + (size_t)tile * 4096))[t + 256 * i];

    int st = 0;
    for (; tile < NT; tile += tstep) {
#pragma unroll
        for (int i = 0; i < 4; i++) {
            int e = t + 256 * i;
            int r = e >> 5, w = e & 31;
            uint32_t h0, h1, l0, l1;
            split2(ap[i].x, ap[i].y, h0, l0);
            split2(ap[i].z, ap[i].w, h1, l1);
            char* p = smem + OFF_A + st * STAGE_B + r * 272 + w * 8;
            *(uint2*)p = make_uint2(h0, h1);
            *(uint2*)(p + 8704) = make_uint2(l0, l1);
        }
        __syncthreads();

        int nxt = tile + tstep;
        if (nxt < NT) {
#pragma unroll
            for (int i = 0; i < 4; i++)
                ap[i] = ((const float4*)(X + (size_t)nxt * 4096))[t + 256 * i];
        }

        float acc[4][4];
#pragma unroll
        for (int a = 0; a < 4; a++)
#pragma unroll
            for (int c = 0; c < 4; c++) acc[a][c] = 0.f;
        mma_tile(sbase + OFF_A + st * STAGE_B, 8704, sbase + OFF_BHI,
                 lane, warp_m, warp_n, acc);

        int m0 = tile * 32;
        int orow = warp_m * 16 + (lane >> 2);
        if (isq) {
#pragma unroll
            for (int nf = 0; nf < 4; nf++) {
                int col = ocol0 + nf * 8;
                float* d = acc[nf];
                size_t r0 = (size_t)(m0 + orow);
                *(float2*)(g_q + r0 * DD + col) = make_float2(d[0] + bv[nf].x, d[1] + bv[nf].y);
                *(float2*)(g_q + (r0 + 8) * DD + col) = make_float2(d[2] + bv[nf].x, d[3] + bv[nf].y);
            }
        } else {
            int tt = (m0 >> 6) & 127;
            if (tt >= 32) {
#pragma unroll
                for (int nf = 0; nf < 4; nf++) {
                    int col = ocol0 + nf * 8;
                    float* d = acc[nf];
                    size_t r0 = (size_t)(m0 + orow);
                    *(float2*)(g_k + r0 * DD + col) = make_float2(d[0] + bv[nf].x, d[1] + bv[nf].y);
                    *(float2*)(g_k + (r0 + 8) * DD + col) = make_float2(d[2] + bv[nf].x, d[3] + bv[nf].y);
                }
            } else {
#pragma unroll
                for (int nf = 0; nf < 4; nf++) {
                    int col = ocol0 + nf * 8;
                    int wi = col >> 1;
                    float* d = acc[nf];
                    uint32_t h, l;
                    size_t r0 = (size_t)(m0 + orow);
                    split2(d[0] + bv[nf].x, d[1] + bv[nf].y, h, l);
                    g_kbh[r0 * 64 + wi] = h; g_kbl[r0 * 64 + wi] = l;
                    split2(d[2] + bv[nf].x, d[3] + bv[nf].y, h, l);
                    g_kbh[(r0 + 8) * 64 + wi] = h; g_kbl[(r0 + 8) * 64 + wi] = l;
                }
            }
        }
        st ^= 1;
    }
}

// ===========================================================================
// attn_out: fused attention + out-projection, persistent 148 CTAs x 512 thr.
// Block splits into TWO independent 256-thread halves sharing resident Wout;
// each half owns a k-tile buffer + MMA stage and its own pair stream
// (stream = 2*blockIdx + half, stride 296), synced by named barriers only.
// Tail: out rows t<32 from g_kb, striped over the same 296 streams.
// ===========================================================================
static constexpr int F_W       = 0;          // Wout hi 34816 + lo 34816
static constexpr int F_HALF0   = 69632;      // per-half block: KS 33792 + STG 34816
static constexpr int F_HALF_SZ = 68608;
static constexpr int F_SMEM    = F_HALF0 + 2 * F_HALF_SZ;   // 206848

static constexpr int NPAIR   = BB * PP;   // 1536
static constexpr int AO_GRID = 148;
static constexpr int NSTREAM = 2 * AO_GRID;  // 296
static constexpr int NKTAIL  = 1024;         // t<32 32-row tiles

#define BARH() asm volatile("bar.sync %0, 256;" :: "r"(half + 1) : "memory")

__global__ void __launch_bounds__(512, 1)
attn_out(const int* __restrict__ ccc, const float* __restrict__ Wout,
         const float* __restrict__ bout, float* __restrict__ out) {
    extern __shared__ char smem[];
    const uint32_t sbase = smem_to_u32(smem);
    int t = threadIdx.x;
    int half = t >> 8, t2 = t & 255;
    int lane = t & 31, wid2 = t2 >> 5;
    int warp_m = wid2 >> 2, warp_n = wid2 & 3;   // 8 warps per half: 2m x 4n

    char* hmem = smem + F_HALF0 + half * F_HALF_SZ;
    const uint32_t ks_base  = sbase + F_HALF0 + half * F_HALF_SZ;   // 64 x 528B
    const uint32_t stg_base = ks_base + 33792;                       // hi+lo 2x17408

    // ---- Wout split resident (all 512 threads) ----
#pragma unroll
    for (int i = 0; i < 16; i++) {
        int e = t + 512 * i;
        int j = e >> 6, w = e & 63;
        float2 p = *(const float2*)(Wout + 2 * e);
        uint32_t h, l;
        split2(p.x, p.y, h, l);
        *(uint32_t*)(smem + F_W + j * 272 + w * 4) = h;
        *(uint32_t*)(smem + F_W + 34816 + j * 272 + w * 4) = l;
    }

    int stream = blockIdx.x * 2 + half;

    // k-tile cp.async into this half's buffer (2048 16B chunks, 8/thread)
    auto issueKS = [&](int pr) {
        if (pr < NPAIR) {
            const char* src = (const char*)(g_k
                + ((size_t)((pr / PP) * TT + 32 + (pr % PP)) * VV) * DD);
#pragma unroll
            for (int k = 0; k < 8; k++) {
                int c = t2 + 256 * k;
                uint32_t d = ks_base + (c >> 5) * 528 + (c & 31) * 16;
                CP_ASYNC16(d, src + c * 16);
            }
        }
        CP_COMMIT();
    };

    issueKS(stream);           // prime first pair's k
    __syncthreads();           // W resident (ONLY full-block sync)

    int ocol0 = warp_n * 32 + 2 * (lane & 3);
    int orow  = warp_m * 16 + (lane >> 2);
    float2 bv[4];
#pragma unroll
    for (int nf = 0; nf < 4; nf++) bv[nf] = *(const float2*)(bout + ocol0 + nf * 8);

    const float scale = 0.08838834764831845f;
    int vh = t2 >> 3, to = t2 & 7;     // head-in-group (0..31), lane-in-head

    // ---- pair loop (per-half stream) ----
    for (int pair = stream; pair < NPAIR; pair += NSTREAM) {
        CP_WAIT0();
        BARH();                         // k-tile visible; prior MMA reads done
        int b = pair / PP;
        const int* ccb = ccc + b * (VV * NN);

        // attention: two 32-head groups per half
#pragma unroll
        for (int h2 = 0; h2 < 2; h2++) {
            int v = h2 * 32 + vh;
            const float4* qrow = (const float4*)(g_q + ((size_t)pair * VV + v) * DD);
            float4 q4[4];
#pragma unroll
            for (int j = 0; j < 4; j++) q4[j] = qrow[to + 8 * j];
            const int* cv = ccb + v * NN;
            float S = 0.f;
            float4 o[4];
#pragma unroll
            for (int j = 0; j < 4; j++) o[j] = make_float4(0.f, 0.f, 0.f, 0.f);
#pragma unroll
            for (int n = 0; n < NN; n++) {
                const char* kr = hmem + cv[n] * 528;
                float4 kv[4];
                float dot = 0.f;
#pragma unroll
                for (int j = 0; j < 4; j++) {
                    kv[j] = *(const float4*)(kr + (to + 8 * j) * 16);
                    dot += q4[j].x * kv[j].x + q4[j].y * kv[j].y
                         + q4[j].z * kv[j].z + q4[j].w * kv[j].w;
                }
                dot += __shfl_xor_sync(0xffffffffu, dot, 1);
                dot += __shfl_xor_sync(0xffffffffu, dot, 2);
                dot += __shfl_xor_sync(0xffffffffu, dot, 4);
                float w = __expf(dot * scale);
                S += w;
#pragma unroll
                for (int j = 0; j < 4; j++) {
                    o[j].x += w * kv[j].x;
                    o[j].y += w * kv[j].y;
                    o[j].z += w * kv[j].z;
                    o[j].w += w * kv[j].w;
                }
            }
            float inv = 1.f / S;
#pragma unroll
            for (int j = 0; j < 4; j++) {
                uint32_t h0, h1, l0, l1;
                split2(o[j].x * inv, o[j].y * inv, h0, l0);
                split2(o[j].z * inv, o[j].w * inv, h1, l1);
                char* d = hmem + 33792 + v * 272 + (to + 8 * j) * 8;
                *(uint2*)d = make_uint2(h0, h1);
                *(uint2*)(d + 17408) = make_uint2(l0, l1);
            }
        }
        BARH();                         // k reads done + stage complete
        issueKS(pair + NSTREAM);        // next k rides under the MMA

        // out-projection MMA: 64 rows as two 32-row passes (8 warps, 2m x 4n)
        size_t ob = (size_t)b * 8192 + (size_t)(32 + pair % PP) * 64;
#pragma unroll
        for (int mo = 0; mo < 2; mo++) {
            float acc[4][4];
#pragma unroll
            for (int a = 0; a < 4; a++)
#pragma unroll
                for (int c = 0; c < 4; c++) acc[a][c] = 0.f;
            mma_tile(stg_base + mo * 8704, 17408, sbase + F_W,
                     lane, warp_m, warp_n, acc);
            size_t rb = ob + mo * 32 + orow;
#pragma unroll
            for (int nf = 0; nf < 4; nf++) {
                int col = ocol0 + nf * 8;
                float* d = acc[nf];
                *(float2*)(out + rb * DD + col) =
                    make_float2(d[0] + bv[nf].x, d[1] + bv[nf].y);
                *(float2*)(out + (rb + 8) * DD + col) =
                    make_float2(d[2] + bv[nf].x, d[3] + bv[nf].y);
            }
        }
    }

    // ---- tail: out rows t<32 from g_kb (32-row tiles over 296 streams) ----
    BARH();                             // last pair's stage reads done
    for (int tile = stream; tile < NKTAIL; tile += NSTREAM) {
        int m0 = (tile >> 6) * 8192 + (tile & 63) * 32;
        // 1024 chunks: hi 512 (32 rows x 16) + lo 512, 4 per thread
#pragma unroll
        for (int k = 0; k < 4; k++) {
            int c = t2 + 256 * k;
            int hl = c >> 9, cd = c & 511;
            int row = cd >> 4, off = cd & 15;
            const uint32_t* src = (hl ? g_kbl : g_kbh)
                                + (size_t)(m0 + row) * 64 + off * 4;
            uint32_t d = stg_base + hl * 17408 + row * 272 + off * 16;
            CP_ASYNC16(d, src);
        }
        CP_COMMIT();
        CP_WAIT0();
        BARH();

        float acc[4][4];
#pragma unroll
        for (int a = 0; a < 4; a++)
#pragma unroll
            for (int c = 0; c < 4; c++) acc[a][c] = 0.f;
        mma_tile(stg_base, 17408, sbase + F_W, lane, warp_m, warp_n, acc);

        size_t rb = (size_t)(m0 + orow);
#pragma unroll
        for (int nf = 0; nf < 4; nf++) {
            int col = ocol0 + nf * 8;
            float* d = acc[nf];
            *(float2*)(out + rb * DD + col) =
                make_float2(d[0] + bv[nf].x, d[1] + bv[nf].y);
            *(float2*)(out + (rb + 8) * DD + col) =
                make_float2(d[2] + bv[nf].x, d[3] + bv[nf].y);
        }
        BARH();                          // stage reads done before next writes
    }
}

// ---------------------------------------------------------------------------
extern "C" void kernel_launch(void* const* d_in, const int* in_sizes, int n_in,
                              void* d_out, int out_size) {
    const float* queries = (const float*)d_in[0];
    const float* keys    = (const float*)d_in[1];
    const int*   ccc     = (const int*)  d_in[2];
    const float* Wq      = (const float*)d_in[3];
    const float* bq      = (const float*)d_in[4];
    const float* Wkv     = (const float*)d_in[5];
    const float* bkv     = (const float*)d_in[6];
    const float* Wout    = (const float*)d_in[7];
    const float* bout    = (const float*)d_in[8];
    float* out = (float*)d_out;

    static bool attr_done = false;
    if (!attr_done) {
        cudaFuncSetAttribute(gemm_qk,  cudaFuncAttributeMaxDynamicSharedMemorySize, GEMM_SMEM);
        cudaFuncSetAttribute(attn_out, cudaFuncAttributeMaxDynamicSharedMemorySize, F_SMEM);
        attr_done = true;
    }

    gemm_qk<<<NCTA, 256, GEMM_SMEM>>>(queries, keys, Wq, Wkv, bq, bkv);
    attn_out<<<AO_GRID, 512, F_SMEM>>>(ccc, Wout, bout, out);
}

// round 13
// speedup vs baseline: 1.0754x; 1.0754x over previous
#include <cuda_runtime.h>
#include <cuda_bf16.h>
#include <cstdint>

#define BB 16
#define PP 96
#define TT 128
#define VV 64
#define NN 16
#define DD 128

// ---------------------------------------------------------------------------
// PTX helpers
// ---------------------------------------------------------------------------
__device__ __forceinline__ uint32_t smem_to_u32(const void* p) {
    uint32_t a;
    asm("{ .reg .u64 t; cvta.to.shared.u64 t, %1; cvt.u32.u64 %0, t; }"
        : "=r"(a) : "l"(p));
    return a;
}
__device__ __forceinline__ void ldsm4(uint32_t* r, uint32_t addr) {
    asm volatile("ldmatrix.sync.aligned.m8n8.x4.shared.b16 {%0,%1,%2,%3}, [%4];"
        : "=r"(r[0]), "=r"(r[1]), "=r"(r[2]), "=r"(r[3]) : "r"(addr));
}
__device__ __forceinline__ void mma_bf16(float* d, const uint32_t* a,
                                         const uint32_t* b) {
    asm volatile(
        "mma.sync.aligned.m16n8k16.row.col.f32.bf16.bf16.f32 "
        "{%0,%1,%2,%3}, {%4,%5,%6,%7}, {%8,%9}, {%0,%1,%2,%3};"
        : "+f"(d[0]), "+f"(d[1]), "+f"(d[2]), "+f"(d[3])
        : "r"(a[0]), "r"(a[1]), "r"(a[2]), "r"(a[3]), "r"(b[0]), "r"(b[1]));
}
#define CVT_BF2(w, xhi, xlo) \
    asm("cvt.rn.bf16x2.f32 %0, %1, %2;" : "=r"(w) : "f"(xhi), "f"(xlo))
#define CP_ASYNC16(dst, src) \
    asm volatile("cp.async.ca.shared.global [%0], [%1], 16;" :: "r"(dst), "l"(src))
#define CP_COMMIT() asm volatile("cp.async.commit_group;" ::: "memory")
#define CP_WAIT0()  asm volatile("cp.async.wait_group 0;" ::: "memory")

// split fp32 pair -> hi bf16x2 word + lo residual word (low half = x0)
__device__ __forceinline__ void split2(float x0, float x1, uint32_t& h, uint32_t& l) {
    CVT_BF2(h, x1, x0);
    float f0 = __uint_as_float(h << 16);
    float f1 = __uint_as_float(h & 0xFFFF0000u);
    CVT_BF2(l, x1 - f1, x0 - f0);
}

// ---------------------------------------------------------------------------
// Scratch
// ---------------------------------------------------------------------------
__device__ float g_q[BB*PP*VV*DD];        // projected queries fp32
__device__ uint32_t g_kbh[BB*TT*VV*64];   // projected keys hi bf16x2 (t<32 rows)
__device__ uint32_t g_kbl[BB*TT*VV*64];

// ---------------------------------------------------------------------------
// Split-bf16 warp-tile MMA over a 272B-stride A stage + resident W (hi at
// w_base, lo at w_base+34816). 16x32 warp tile at (warp_m, warp_n).
// ---------------------------------------------------------------------------
__device__ __forceinline__ void mma_tile(uint32_t a_base, int a_lo_off,
                                         uint32_t w_base, int lane,
                                         int warp_m, int warp_n, float acc[4][4]) {
    uint32_t a0 = a_base + (uint32_t)(warp_m * 16 + (lane & 15)) * 272
                + ((lane >> 4) * 16);
    int bj = warp_n * 32 + (lane & 7) + ((lane >> 4) * 8);
    uint32_t b0 = w_base + (uint32_t)bj * 272 + (((lane >> 3) & 1) * 16);
#pragma unroll
    for (int ks = 0; ks < 8; ks++) {
        uint32_t ah[4], al[4], bh[2][4], bl[2][4];
        ldsm4(ah, a0 + ks * 32);
        ldsm4(al, a0 + a_lo_off + ks * 32);
        ldsm4(bh[0], b0 + ks * 32);
        ldsm4(bh[1], b0 + 16 * 272 + ks * 32);
        ldsm4(bl[0], b0 + 34816 + ks * 32);
        ldsm4(bl[1], b0 + 34816 + 16 * 272 + ks * 32);
#pragma unroll
        for (int ni = 0; ni < 2; ni++)
#pragma unroll
            for (int s2 = 0; s2 < 2; s2++) {
                float* d = acc[2 * ni + s2];
                mma_bf16(d, ah, &bh[ni][2 * s2]);
                mma_bf16(d, ah, &bl[ni][2 * s2]);
                mma_bf16(d, al, &bh[ni][2 * s2]);
            }
    }
}

// ===========================================================================
// gemm_q: persistent projection GEMM, two partitions.
//   CTAs [0,222):   q = queries@Wq^T + bq           -> g_q    (3072 tiles)
//   CTAs [222,296): k(t<32) = keys@Wkv^T + bkv      -> g_kb   (1024 tiles, bf16 split)
// ===========================================================================
static constexpr int OFF_BHI  = 0;
static constexpr int OFF_BLO  = 34816;
static constexpr int OFF_A    = 69632;
static constexpr int STAGE_B  = 17408;
static constexpr int GEMM_SMEM = OFF_A + 2 * STAGE_B;   // 104448

static constexpr int NCTA = 296;
static constexpr int NQC  = 222;
static constexpr int NKC  = NCTA - NQC;   // 74
static constexpr int NQT  = BB*PP*VV/32;  // 3072
static constexpr int NKBT = 1024;         // t<32 tiles

__device__ __forceinline__ void load_W256(char* smem, const float* __restrict__ W, int t) {
#pragma unroll
    for (int i = 0; i < 32; i++) {
        int e = t + 256 * i;
        int j = e >> 6, w = e & 63;
        float2 p = *(const float2*)(W + 2 * e);
        uint32_t h, l;
        split2(p.x, p.y, h, l);
        *(uint32_t*)(smem + OFF_BHI + j * 272 + w * 4) = h;
        *(uint32_t*)(smem + OFF_BLO + j * 272 + w * 4) = l;
    }
}

__global__ void __launch_bounds__(256, 2)
gemm_q(const float* __restrict__ queries, const float* __restrict__ keys,
       const float* __restrict__ Wq, const float* __restrict__ Wkv,
       const float* __restrict__ bq, const float* __restrict__ bkv) {
    extern __shared__ char smem[];
    const uint32_t sbase = smem_to_u32(smem);
    int t = threadIdx.x, lane = t & 31, wid = t >> 5;
    int warp_m = wid >> 2, warp_n = wid & 3;
    int cta = blockIdx.x;
    bool isq = cta < NQC;
    int tile  = isq ? cta : cta - NQC;
    int tstep = isq ? NQC : NKC;
    int NT    = isq ? NQT : NKBT;
    const float* X    = isq ? queries : keys;
    const float* bias = isq ? bq : bkv;

    load_W256(smem, isq ? Wq : Wkv, t);

    auto rowof = [&](int tl) -> int {
        return isq ? tl * 32 : ((tl >> 6) * 8192 + (tl & 63) * 32);
    };

    int ocol0 = warp_n * 32 + 2 * (lane & 3);
    float2 bv[4];
#pragma unroll
    for (int nf = 0; nf < 4; nf++) bv[nf] = *(const float2*)(bias + ocol0 + nf * 8);

    float4 ap[4];
    if (tile < NT) {
        const float4* src = (const float4*)(X + (size_t)rowof(tile) * DD);
#pragma unroll
        for (int i = 0; i < 4; i++) ap[i] = src[t + 256 * i];
    }

    int st = 0;
    for (; tile < NT; tile += tstep) {
#pragma unroll
        for (int i = 0; i < 4; i++) {
            int e = t + 256 * i;
            int r = e >> 5, w = e & 31;
            uint32_t h0, h1, l0, l1;
            split2(ap[i].x, ap[i].y, h0, l0);
            split2(ap[i].z, ap[i].w, h1, l1);
            char* p = smem + OFF_A + st * STAGE_B + r * 272 + w * 8;
            *(uint2*)p = make_uint2(h0, h1);
            *(uint2*)(p + 8704) = make_uint2(l0, l1);
        }
        __syncthreads();

        int nxt = tile + tstep;
        if (nxt < NT) {
            const float4* src = (const float4*)(X + (size_t)rowof(nxt) * DD);
#pragma unroll
            for (int i = 0; i < 4; i++) ap[i] = src[t + 256 * i];
        }

        float acc[4][4];
#pragma unroll
        for (int a = 0; a < 4; a++)
#pragma unroll
            for (int c = 0; c < 4; c++) acc[a][c] = 0.f;
        mma_tile(sbase + OFF_A + st * STAGE_B, 8704, sbase + OFF_BHI,
                 lane, warp_m, warp_n, acc);

        int m0 = rowof(tile);
        int orow = warp_m * 16 + (lane >> 2);
        if (isq) {
#pragma unroll
            for (int nf = 0; nf < 4; nf++) {
                int col = ocol0 + nf * 8;
                float* d = acc[nf];
                size_t r0 = (size_t)(m0 + orow);
                *(float2*)(g_q + r0 * DD + col) = make_float2(d[0] + bv[nf].x, d[1] + bv[nf].y);
                *(float2*)(g_q + (r0 + 8) * DD + col) = make_float2(d[2] + bv[nf].x, d[3] + bv[nf].y);
            }
        } else {
#pragma unroll
            for (int nf = 0; nf < 4; nf++) {
                int col = ocol0 + nf * 8;
                int wi = col >> 1;
                float* d = acc[nf];
                uint32_t h, l;
                size_t r0 = (size_t)(m0 + orow);
                split2(d[0] + bv[nf].x, d[1] + bv[nf].y, h, l);
                g_kbh[r0 * 64 + wi] = h; g_kbl[r0 * 64 + wi] = l;
                split2(d[2] + bv[nf].x, d[3] + bv[nf].y, h, l);
                g_kbh[(r0 + 8) * 64 + wi] = h; g_kbl[(r0 + 8) * 64 + wi] = l;
            }
        }
        st ^= 1;
    }
}

// ===========================================================================
// attn_out: k-projection + attention + out-projection fused. Persistent
// 148 CTAs x 512 threads (16 warps, 4m x 4n). Wkv AND Wout resident.
// Per pair: keys tile (reg-prefetched) -> convert -> k-proj MMA -> k fp32 in
// SMEM -> attention (q reg-prefetched from g_q) -> attn out -> out-proj MMA
// -> out. Projected k never touches global memory.
// Tail: out rows t<32 from g_kb (cp.async, Wout resident).
// ===========================================================================
static constexpr int F_WK  = 0;          // Wkv hi/lo (34816 + 34816)
static constexpr int F_WO  = 69632;      // Wout hi/lo
static constexpr int F_STG = 139264;     // bf16 A stage: hi 17408 + lo 17408
static constexpr int F_KS  = 174080;     // k fp32 64 x 528B = 33792
static constexpr int F_SMEM = 207872;

static constexpr int NPAIR   = BB * PP;  // 1536
static constexpr int AO_GRID = 148;
static constexpr int NCHUNK  = 512;      // t<32: 1024 32-row tiles, 2 per chunk

__global__ void __launch_bounds__(512, 1)
attn_out(const float* __restrict__ keys, const int* __restrict__ ccc,
         const float* __restrict__ Wkv, const float* __restrict__ bkv,
         const float* __restrict__ Wout, const float* __restrict__ bout,
         float* __restrict__ out) {
    extern __shared__ char smem[];
    const uint32_t sbase = smem_to_u32(smem);
    int t = threadIdx.x, lane = t & 31, wid = t >> 5;
    int warp_m = wid >> 2, warp_n = wid & 3;

    // ---- both weights split-resident (once per CTA) ----
#pragma unroll
    for (int i = 0; i < 16; i++) {
        int e = t + 512 * i;
        int j = e >> 6, w = e & 63;
        float2 p = *(const float2*)(Wkv + 2 * e);
        uint32_t h, l;
        split2(p.x, p.y, h, l);
        *(uint32_t*)(smem + F_WK + j * 272 + w * 4) = h;
        *(uint32_t*)(smem + F_WK + 34816 + j * 272 + w * 4) = l;
        float2 p2 = *(const float2*)(Wout + 2 * e);
        split2(p2.x, p2.y, h, l);
        *(uint32_t*)(smem + F_WO + j * 272 + w * 4) = h;
        *(uint32_t*)(smem + F_WO + 34816 + j * 272 + w * 4) = l;
    }

    int ocol0 = warp_n * 32 + 2 * (lane & 3);
    int orow  = warp_m * 16 + (lane >> 2);
    float2 bvK[4], bvO[4];
#pragma unroll
    for (int nf = 0; nf < 4; nf++) {
        bvK[nf] = *(const float2*)(bkv + ocol0 + nf * 8);
        bvO[nf] = *(const float2*)(bout + ocol0 + nf * 8);
    }

    const float scale = 0.08838834764831845f;
    int v = t >> 3, to = t & 7;

    // ---- prefetch first pair: raw keys tile + q row slice ----
    int pair = blockIdx.x;
    float4 kp[4], q4[4], qn[4];
    if (pair < NPAIR) {
        const float4* ksrc = (const float4*)keys
            + (size_t)((pair / PP) * TT + 32 + (pair % PP)) * 2048;
#pragma unroll
        for (int i = 0; i < 4; i++) kp[i] = ksrc[t + 512 * i];
        const float4* qrow = (const float4*)(g_q + ((size_t)pair * VV + v) * DD);
#pragma unroll
        for (int j = 0; j < 4; j++) q4[j] = qrow[to + 8 * j];
    }
    __syncthreads();            // weights resident

    for (; pair < NPAIR; pair += AO_GRID) {
        int b = pair / PP;

        // ---- convert raw keys -> bf16 split stage ----
#pragma unroll
        for (int i = 0; i < 4; i++) {
            int e = t + 512 * i;
            int r = e >> 5, c4 = e & 31;
            uint32_t h0, h1, l0, l1;
            split2(kp[i].x, kp[i].y, h0, l0);
            split2(kp[i].z, kp[i].w, h1, l1);
            char* dst = smem + F_STG + r * 272 + c4 * 8;
            *(uint2*)dst = make_uint2(h0, h1);
            *(uint2*)(dst + 17408) = make_uint2(l0, l1);
        }
        // prefetch next pair's raw keys (rides under both MMAs)
        int np = pair + AO_GRID;
        if (np < NPAIR) {
            const float4* ksrc = (const float4*)keys
                + (size_t)((np / PP) * TT + 32 + (np % PP)) * 2048;
#pragma unroll
            for (int i = 0; i < 4; i++) kp[i] = ksrc[t + 512 * i];
        }
        __syncthreads();

        // ---- k-projection MMA (16 warps, 64x128) -> k fp32 into F_KS ----
        {
            float acc[4][4];
#pragma unroll
            for (int a = 0; a < 4; a++)
#pragma unroll
                for (int c = 0; c < 4; c++) acc[a][c] = 0.f;
            mma_tile(sbase + F_STG, 17408, sbase + F_WK, lane, warp_m, warp_n, acc);
#pragma unroll
            for (int nf = 0; nf < 4; nf++) {
                int col = ocol0 + nf * 8;
                float* d = acc[nf];
                *(float2*)(smem + F_KS + orow * 528 + col * 4) =
                    make_float2(d[0] + bvK[nf].x, d[1] + bvK[nf].y);
                *(float2*)(smem + F_KS + (orow + 8) * 528 + col * 4) =
                    make_float2(d[2] + bvK[nf].x, d[3] + bvK[nf].y);
            }
        }
        __syncthreads();        // k tile complete; k-proj stage reads done

        // ---- attention (8 threads/head) ----
        const int* cv = ccc + b * (VV * NN) + v * NN;
        float S = 0.f;
        float4 o[4];
#pragma unroll
        for (int j = 0; j < 4; j++) o[j] = make_float4(0.f, 0.f, 0.f, 0.f);
#pragma unroll
        for (int n = 0; n < NN; n++) {
            const char* kr = smem + F_KS + cv[n] * 528;
            float4 kv[4];
            float dot = 0.f;
#pragma unroll
            for (int j = 0; j < 4; j++) {
                kv[j] = *(const float4*)(kr + (to + 8 * j) * 16);
                dot += q4[j].x * kv[j].x + q4[j].y * kv[j].y
                     + q4[j].z * kv[j].z + q4[j].w * kv[j].w;
            }
            dot += __shfl_xor_sync(0xffffffffu, dot, 1);
            dot += __shfl_xor_sync(0xffffffffu, dot, 2);
            dot += __shfl_xor_sync(0xffffffffu, dot, 4);
            float w = __expf(dot * scale);
            S += w;
#pragma unroll
            for (int j = 0; j < 4; j++) {
                o[j].x += w * kv[j].x;
                o[j].y += w * kv[j].y;
                o[j].z += w * kv[j].z;
                o[j].w += w * kv[j].w;
            }
        }
        // attn output -> bf16 split stage (row = head v); stage free post-MMAk
        float inv = 1.f / S;
#pragma unroll
        for (int j = 0; j < 4; j++) {
            uint32_t h0, h1, l0, l1;
            split2(o[j].x * inv, o[j].y * inv, h0, l0);
            split2(o[j].z * inv, o[j].w * inv, h1, l1);
            char* d = smem + F_STG + v * 272 + (to + 8 * j) * 8;
            *(uint2*)d = make_uint2(h0, h1);
            *(uint2*)(d + 17408) = make_uint2(l0, l1);
        }
        // prefetch next pair's q (rides under out-proj MMA)
        if (np < NPAIR) {
            const float4* qrow = (const float4*)(g_q + ((size_t)np * VV + v) * DD);
#pragma unroll
            for (int j = 0; j < 4; j++) qn[j] = qrow[to + 8 * j];
        }
        __syncthreads();        // stage complete; KS reads done

        // ---- out-projection MMA (16 warps, 64x128) -> out ----
        {
            float acc[4][4];
#pragma unroll
            for (int a = 0; a < 4; a++)
#pragma unroll
                for (int c = 0; c < 4; c++) acc[a][c] = 0.f;
            mma_tile(sbase + F_STG, 17408, sbase + F_WO, lane, warp_m, warp_n, acc);
            size_t ob = (size_t)b * 8192 + (size_t)(32 + pair % PP) * 64;
#pragma unroll
            for (int nf = 0; nf < 4; nf++) {
                int col = ocol0 + nf * 8;
                float* d = acc[nf];
                *(float2*)(out + (ob + orow) * DD + col) =
                    make_float2(d[0] + bvO[nf].x, d[1] + bvO[nf].y);
                *(float2*)(out + (ob + orow + 8) * DD + col) =
                    make_float2(d[2] + bvO[nf].x, d[3] + bvO[nf].y);
            }
        }
#pragma unroll
        for (int j = 0; j < 4; j++) q4[j] = qn[j];
        __syncthreads();        // out-proj stage reads done before next convert
    }

    // ---- tail: out rows t<32 from g_kb (2 x 32-row tiles per chunk) ----
    int g2 = wid >> 3, w7 = wid & 7;
    int warp_m2 = w7 >> 2;               // warp_n unchanged (wid&3) -> bvO valid
    int orow2 = warp_m2 * 16 + (lane >> 2);
    int t2 = t & 255;  // not used for barriers; index helper only

    for (int ch = blockIdx.x; ch < NCHUNK; ch += AO_GRID) {
        int m0a = ((2 * ch) >> 6) * 8192 + ((2 * ch) & 63) * 32;
        int m0b = ((2 * ch + 1) >> 6) * 8192 + ((2 * ch + 1) & 63) * 32;
#pragma unroll
        for (int k = 0; k < 4; k++) {
            int c = t + 512 * k;             // 0..2047
            int g = c >> 10, cc = c & 1023;
            int half = cc >> 9, cd = cc & 511;
            int row = cd >> 4, off = cd & 15;
            int m0 = g ? m0b : m0a;
            const uint32_t* src = (half ? g_kbl : g_kbh) + (size_t)(m0 + row) * 64 + off * 4;
            uint32_t d = sbase + F_STG + g * 8704 + half * 17408 + row * 272 + off * 16;
            CP_ASYNC16(d, src);
        }
        CP_COMMIT();
        CP_WAIT0();
        __syncthreads();

        float acc[4][4];
#pragma unroll
        for (int a = 0; a < 4; a++)
#pragma unroll
            for (int c = 0; c < 4; c++) acc[a][c] = 0.f;
        mma_tile(sbase + F_STG + g2 * 8704, 17408, sbase + F_WO,
                 lane, warp_m2, warp_n, acc);

        int m0 = g2 ? m0b : m0a;
#pragma unroll
        for (int nf = 0; nf < 4; nf++) {
            int col = ocol0 + nf * 8;
            float* d = acc[nf];
            size_t r0 = (size_t)(m0 + orow2);
            *(float2*)(out + r0 * DD + col) =
                make_float2(d[0] + bvO[nf].x, d[1] + bvO[nf].y);
            *(float2*)(out + (r0 + 8) * DD + col) =
                make_float2(d[2] + bvO[nf].x, d[3] + bvO[nf].y);
        }
        __syncthreads();
    }
    (void)t2;
}

// ---------------------------------------------------------------------------
extern "C" void kernel_launch(void* const* d_in, const int* in_sizes, int n_in,
                              void* d_out, int out_size) {
    const float* queries = (const float*)d_in[0];
    const float* keys    = (const float*)d_in[1];
    const int*   ccc     = (const int*)  d_in[2];
    const float* Wq      = (const float*)d_in[3];
    const float* bq      = (const float*)d_in[4];
    const float* Wkv     = (const float*)d_in[5];
    const float* bkv     = (const float*)d_in[6];
    const float* Wout    = (const float*)d_in[7];
    const float* bout    = (const float*)d_in[8];
    float* out = (float*)d_out;

    static bool attr_done = false;
    if (!attr_done) {
        cudaFuncSetAttribute(gemm_q,   cudaFuncAttributeMaxDynamicSharedMemorySize, GEMM_SMEM);
        cudaFuncSetAttribute(attn_out, cudaFuncAttributeMaxDynamicSharedMemorySize, F_SMEM);
        attr_done = true;
    }

    gemm_q<<<NCTA, 256, GEMM_SMEM>>>(queries, keys, Wq, Wkv, bq, bkv);
    attn_out<<<AO_GRID, 512, F_SMEM>>>(keys, ccc, Wkv, bkv, Wout, bout, out);
}

// round 14
// speedup vs baseline: 1.0983x; 1.0213x over previous
#include <cuda_runtime.h>
#include <cuda_bf16.h>
#include <cstdint>

#define BB 16
#define PP 96
#define TT 128
#define VV 64
#define NN 16
#define DD 128

// ---------------------------------------------------------------------------
// PTX helpers
// ---------------------------------------------------------------------------
__device__ __forceinline__ uint32_t smem_to_u32(const void* p) {
    uint32_t a;
    asm("{ .reg .u64 t; cvta.to.shared.u64 t, %1; cvt.u32.u64 %0, t; }"
        : "=r"(a) : "l"(p));
    return a;
}
__device__ __forceinline__ void ldsm4(uint32_t* r, uint32_t addr) {
    asm volatile("ldmatrix.sync.aligned.m8n8.x4.shared.b16 {%0,%1,%2,%3}, [%4];"
        : "=r"(r[0]), "=r"(r[1]), "=r"(r[2]), "=r"(r[3]) : "r"(addr));
}
__device__ __forceinline__ void ldsm4t(uint32_t* r, uint32_t addr) {
    asm volatile("ldmatrix.sync.aligned.m8n8.x4.trans.shared.b16 {%0,%1,%2,%3}, [%4];"
        : "=r"(r[0]), "=r"(r[1]), "=r"(r[2]), "=r"(r[3]) : "r"(addr));
}
__device__ __forceinline__ void mma_bf16(float* d, const uint32_t* a,
                                         const uint32_t* b) {
    asm volatile(
        "mma.sync.aligned.m16n8k16.row.col.f32.bf16.bf16.f32 "
        "{%0,%1,%2,%3}, {%4,%5,%6,%7}, {%8,%9}, {%0,%1,%2,%3};"
        : "+f"(d[0]), "+f"(d[1]), "+f"(d[2]), "+f"(d[3])
        : "r"(a[0]), "r"(a[1]), "r"(a[2]), "r"(a[3]), "r"(b[0]), "r"(b[1]));
}
#define CVT_BF2(w, xhi, xlo) \
    asm("cvt.rn.bf16x2.f32 %0, %1, %2;" : "=r"(w) : "f"(xhi), "f"(xlo))
#define CP_ASYNC16(dst, src) \
    asm volatile("cp.async.ca.shared.global [%0], [%1], 16;" :: "r"(dst), "l"(src))
#define CP_COMMIT() asm volatile("cp.async.commit_group;" ::: "memory")
#define CP_WAIT0()  asm volatile("cp.async.wait_group 0;" ::: "memory")

// split fp32 pair -> hi bf16x2 word + lo residual word (low half = x0)
__device__ __forceinline__ void split2(float x0, float x1, uint32_t& h, uint32_t& l) {
    CVT_BF2(h, x1, x0);
    float f0 = __uint_as_float(h << 16);
    float f1 = __uint_as_float(h & 0xFFFF0000u);
    CVT_BF2(l, x1 - f1, x0 - f0);
}

// ---------------------------------------------------------------------------
// Scratch
// ---------------------------------------------------------------------------
__device__ float g_q[BB*PP*VV*DD];        // projected queries fp32
__device__ float g_k[BB*TT*VV*DD];        // projected keys fp32 (t>=32 rows used)
__device__ uint32_t g_kbh[BB*TT*VV*64];   // projected keys hi bf16x2 (t<32 rows)
__device__ uint32_t g_kbl[BB*TT*VV*64];

// ---------------------------------------------------------------------------
// Split-bf16 warp-tile MMA (16x32 warp tile) over a 272B-stride A stage +
// resident W (hi at w_base, lo at w_base+34816), K=128.
// ---------------------------------------------------------------------------
__device__ __forceinline__ void mma_tile(uint32_t a_base, int a_lo_off,
                                         uint32_t w_base, int lane,
                                         int warp_m, int warp_n, float acc[4][4]) {
    uint32_t a0 = a_base + (uint32_t)(warp_m * 16 + (lane & 15)) * 272
                + ((lane >> 4) * 16);
    int bj = warp_n * 32 + (lane & 7) + ((lane >> 4) * 8);
    uint32_t b0 = w_base + (uint32_t)bj * 272 + (((lane >> 3) & 1) * 16);
#pragma unroll
    for (int ks = 0; ks < 8; ks++) {
        uint32_t ah[4], al[4], bh[2][4], bl[2][4];
        ldsm4(ah, a0 + ks * 32);
        ldsm4(al, a0 + a_lo_off + ks * 32);
        ldsm4(bh[0], b0 + ks * 32);
        ldsm4(bh[1], b0 + 16 * 272 + ks * 32);
        ldsm4(bl[0], b0 + 34816 + ks * 32);
        ldsm4(bl[1], b0 + 34816 + 16 * 272 + ks * 32);
#pragma unroll
        for (int ni = 0; ni < 2; ni++)
#pragma unroll
            for (int s2 = 0; s2 < 2; s2++) {
                float* d = acc[2 * ni + s2];
                mma_bf16(d, ah, &bh[ni][2 * s2]);
                mma_bf16(d, ah, &bl[ni][2 * s2]);
                mma_bf16(d, al, &bh[ni][2 * s2]);
            }
    }
}

// ===========================================================================
// gemm_qk (round-11 verbatim, measured 76.3us): persistent q/k projection.
// ===========================================================================
static constexpr int OFF_BHI  = 0;
static constexpr int OFF_BLO  = 34816;
static constexpr int OFF_A    = 69632;
static constexpr int STAGE_B  = 17408;
static constexpr int GEMM_SMEM = OFF_A + 2 * STAGE_B;   // 104448

static constexpr int NCTA = 296;
static constexpr int NQC  = 127;
static constexpr int NKC  = NCTA - NQC;   // 169
static constexpr int NQT  = BB*PP*VV/32;  // 3072
static constexpr int NKT  = BB*TT*VV/32;  // 4096

__device__ __forceinline__ void load_W256(char* smem, const float* __restrict__ W, int t) {
#pragma unroll
    for (int i = 0; i < 32; i++) {
        int e = t + 256 * i;
        int j = e >> 6, w = e & 63;
        float2 p = *(const float2*)(W + 2 * e);
        uint32_t h, l;
        split2(p.x, p.y, h, l);
        *(uint32_t*)(smem + OFF_BHI + j * 272 + w * 4) = h;
        *(uint32_t*)(smem + OFF_BLO + j * 272 + w * 4) = l;
    }
}

__global__ void __launch_bounds__(256, 2)
gemm_qk(const float* __restrict__ queries, const float* __restrict__ keys,
        const float* __restrict__ Wq, const float* __restrict__ Wkv,
        const float* __restrict__ bq, const float* __restrict__ bkv) {
    extern __shared__ char smem[];
    const uint32_t sbase = smem_to_u32(smem);
    int t = threadIdx.x, lane = t & 31, wid = t >> 5;
    int warp_m = wid >> 2, warp_n = wid & 3;
    int cta = blockIdx.x;
    bool isq = cta < NQC;
    int tile  = isq ? cta : cta - NQC;
    int tstep = isq ? NQC : NKC;
    int NT    = isq ? NQT : NKT;
    const float* X    = isq ? queries : keys;
    const float* bias = isq ? bq : bkv;

    load_W256(smem, isq ? Wq : Wkv, t);

    int ocol0 = warp_n * 32 + 2 * (lane & 3);
    float2 bv[4];
#pragma unroll
    for (int nf = 0; nf < 4; nf++) bv[nf] = *(const float2*)(bias + ocol0 + nf * 8);

    float4 ap[4];
#pragma unroll
    for (int i = 0; i < 4; i++)
        ap[i] = ((const float4*)(X + (size_t)tile * 4096))[t + 256 * i];

    int st = 0;
    for (; tile < NT; tile += tstep) {
#pragma unroll
        for (int i = 0; i < 4; i++) {
            int e = t + 256 * i;
            int r = e >> 5, w = e & 31;
            uint32_t h0, h1, l0, l1;
            split2(ap[i].x, ap[i].y, h0, l0);
            split2(ap[i].z, ap[i].w, h1, l1);
            char* p = smem + OFF_A + st * STAGE_B + r * 272 + w * 8;
            *(uint2*)p = make_uint2(h0, h1);
            *(uint2*)(p + 8704) = make_uint2(l0, l1);
        }
        __syncthreads();

        int nxt = tile + tstep;
        if (nxt < NT) {
#pragma unroll
            for (int i = 0; i < 4; i++)
                ap[i] = ((const float4*)(X + (size_t)nxt * 4096))[t + 256 * i];
        }

        float acc[4][4];
#pragma unroll
        for (int a = 0; a < 4; a++)
#pragma unroll
            for (int c = 0; c < 4; c++) acc[a][c] = 0.f;
        mma_tile(sbase + OFF_A + st * STAGE_B, 8704, sbase + OFF_BHI,
                 lane, warp_m, warp_n, acc);

        int m0 = tile * 32;
        int orow = warp_m * 16 + (lane >> 2);
        if (isq) {
#pragma unroll
            for (int nf = 0; nf < 4; nf++) {
                int col = ocol0 + nf * 8;
                float* d = acc[nf];
                size_t r0 = (size_t)(m0 + orow);
                *(float2*)(g_q + r0 * DD + col) = make_float2(d[0] + bv[nf].x, d[1] + bv[nf].y);
                *(float2*)(g_q + (r0 + 8) * DD + col) = make_float2(d[2] + bv[nf].x, d[3] + bv[nf].y);
            }
        } else {
            int tt = (m0 >> 6) & 127;
            if (tt >= 32) {
#pragma unroll
                for (int nf = 0; nf < 4; nf++) {
                    int col = ocol0 + nf * 8;
                    float* d = acc[nf];
                    size_t r0 = (size_t)(m0 + orow);
                    *(float2*)(g_k + r0 * DD + col) = make_float2(d[0] + bv[nf].x, d[1] + bv[nf].y);
                    *(float2*)(g_k + (r0 + 8) * DD + col) = make_float2(d[2] + bv[nf].x, d[3] + bv[nf].y);
                }
            } else {
#pragma unroll
                for (int nf = 0; nf < 4; nf++) {
                    int col = ocol0 + nf * 8;
                    int wi = col >> 1;
                    float* d = acc[nf];
                    uint32_t h, l;
                    size_t r0 = (size_t)(m0 + orow);
                    split2(d[0] + bv[nf].x, d[1] + bv[nf].y, h, l);
                    g_kbh[r0 * 64 + wi] = h; g_kbl[r0 * 64 + wi] = l;
                    split2(d[2] + bv[nf].x, d[3] + bv[nf].y, h, l);
                    g_kbh[(r0 + 8) * 64 + wi] = h; g_kbl[(r0 + 8) * 64 + wi] = l;
                }
            }
        }
        st ^= 1;
    }
}

// ===========================================================================
// attn_out: GEMM-formulated attention + out-projection, persistent 148 CTAs
// x 512 thr (16 warps, 4m x 4n). Per pair:
//   S = q @ k^T (64x64x128 split MMA) -> gather/softmax/scatter -> dense W
//   O = W @ k   (64x128x64 split MMA, B via ldsm.trans from row-major k)
//   out = O @ Wout^T + bout
// Tail: out rows t<32 from g_kb (round-11 verbatim).
// ===========================================================================
static constexpr int F_WO  = 0;          // Wout hi/lo (34816+34816)
static constexpr int F_QS  = 69632;      // q stage hi/lo (17408+17408); O stage reuses
static constexpr int F_KR  = 104448;     // k stage hi/lo (row-major, 272B)
static constexpr int F_WF  = 139264;     // W fp32 scatter buffer (64 x 272B)
static constexpr int F_WS  = 156672;     // W split (64 x 144B) hi + lo(+9216)
static constexpr int F_S   = 175104;     // S fp32 (64 x 272B)
static constexpr int F_SMEM = 192512;

static constexpr int NPAIR   = BB * PP;  // 1536
static constexpr int AO_GRID = 148;
static constexpr int NCHUNK  = 512;      // t<32: 1024 32-row tiles, 2 per chunk

// S-GEMM: 64x64x128, warp tile 16x16. A=q stage, B=k stage (both 272B, K-major)
__device__ __forceinline__ void mma_S(uint32_t q_base, uint32_t k_base, int lane,
                                      int warp_m, int warp_n, float acc[2][4]) {
    uint32_t a0 = q_base + (uint32_t)(warp_m * 16 + (lane & 15)) * 272
                + ((lane >> 4) * 16);
    uint32_t b0 = k_base + (uint32_t)(warp_n * 16 + (lane & 7) + ((lane >> 4) * 8)) * 272
                + (((lane >> 3) & 1) * 16);
#pragma unroll
    for (int ks = 0; ks < 8; ks++) {
        uint32_t ah[4], al[4], bh[4], bl[4];
        ldsm4(ah, a0 + ks * 32);
        ldsm4(al, a0 + 17408 + ks * 32);
        ldsm4(bh, b0 + ks * 32);
        ldsm4(bl, b0 + 17408 + ks * 32);
#pragma unroll
        for (int s2 = 0; s2 < 2; s2++) {
            float* d = acc[s2];
            mma_bf16(d, ah, &bh[2 * s2]);
            mma_bf16(d, ah, &bl[2 * s2]);
            mma_bf16(d, al, &bh[2 * s2]);
        }
    }
}

// O-GEMM: 64x128x64, warp tile 16x32. A = W split (144B stride), B = k stage
// row-major [r][d] loaded via ldmatrix.trans (r = k-dim, d = n-dim).
__device__ __forceinline__ void mma_O(uint32_t w_base, uint32_t k_base, int lane,
                                      int warp_m, int warp_n, float acc[4][4]) {
    uint32_t a0 = w_base + (uint32_t)(warp_m * 16 + (lane & 15)) * 144
                + ((lane >> 4) * 16);
    uint32_t b0 = k_base + (uint32_t)(lane & 15) * 272
                + (uint32_t)(warp_n * 32 + (lane >> 4) * 8) * 2;
#pragma unroll
    for (int ks = 0; ks < 4; ks++) {
        uint32_t ah[4], al[4], bh[2][4], bl[2][4];
        ldsm4(ah, a0 + ks * 32);
        ldsm4(al, a0 + 9216 + ks * 32);
#pragma unroll
        for (int ni = 0; ni < 2; ni++) {
            uint32_t ba = b0 + (uint32_t)ks * 16 * 272 + ni * 32;
            ldsm4t(bh[ni], ba);
            ldsm4t(bl[ni], ba + 17408);
        }
#pragma unroll
        for (int ni = 0; ni < 2; ni++)
#pragma unroll
            for (int s2 = 0; s2 < 2; s2++) {
                float* d = acc[2 * ni + s2];
                mma_bf16(d, ah, &bh[ni][2 * s2]);
                mma_bf16(d, ah, &bl[ni][2 * s2]);
                mma_bf16(d, al, &bh[ni][2 * s2]);
            }
    }
}

__global__ void __launch_bounds__(512, 1)
attn_out(const int* __restrict__ ccc, const float* __restrict__ Wout,
         const float* __restrict__ bout, float* __restrict__ out) {
    extern __shared__ char smem[];
    const uint32_t sbase = smem_to_u32(smem);
    int t = threadIdx.x, lane = t & 31, wid = t >> 5;
    int warp_m = wid >> 2, warp_n = wid & 3;

    // ---- first pair prefetch (before W-load barrier) ----
    int pair = blockIdx.x;
    float4 kp[4], qp[4];
    {
        const float4* ks = (const float4*)(g_k
            + ((size_t)((pair / PP) * TT + 32 + (pair % PP)) * VV) * DD);
        const float4* qs = (const float4*)(g_q + (size_t)pair * VV * DD);
#pragma unroll
        for (int i = 0; i < 4; i++) { kp[i] = ks[t + 512 * i]; qp[i] = qs[t + 512 * i]; }
    }

    // ---- Wout split resident ----
#pragma unroll
    for (int i = 0; i < 16; i++) {
        int e = t + 512 * i;
        int j = e >> 6, w = e & 63;
        float2 p = *(const float2*)(Wout + 2 * e);
        uint32_t h, l;
        split2(p.x, p.y, h, l);
        *(uint32_t*)(smem + F_WO + j * 272 + w * 4) = h;
        *(uint32_t*)(smem + F_WO + 34816 + j * 272 + w * 4) = l;
    }

    int ocol0 = warp_n * 32 + 2 * (lane & 3);
    int orow  = warp_m * 16 + (lane >> 2);
    float2 bv[4];
#pragma unroll
    for (int nf = 0; nf < 4; nf++) bv[nf] = *(const float2*)(bout + ocol0 + nf * 8);

    const float scale = 0.08838834764831845f;
    int v = t >> 3, to = t & 7;
    __syncthreads();        // Wout resident

    for (; pair < NPAIR; pair += AO_GRID) {
        int b = pair / PP;

        // ---- P0: convert k -> F_KR, q -> F_QS; zero W fp32 ----
#pragma unroll
        for (int i = 0; i < 4; i++) {
            int e = t + 512 * i;
            int r = e >> 5, c4 = e & 31;
            uint32_t h0, h1, l0, l1;
            split2(kp[i].x, kp[i].y, h0, l0);
            split2(kp[i].z, kp[i].w, h1, l1);
            char* dk = smem + F_KR + r * 272 + c4 * 8;
            *(uint2*)dk = make_uint2(h0, h1);
            *(uint2*)(dk + 17408) = make_uint2(l0, l1);
            split2(qp[i].x, qp[i].y, h0, l0);
            split2(qp[i].z, qp[i].w, h1, l1);
            char* dq = smem + F_QS + r * 272 + c4 * 8;
            *(uint2*)dq = make_uint2(h0, h1);
            *(uint2*)(dq + 17408) = make_uint2(l0, l1);
        }
#pragma unroll
        for (int i = 0; i < 8; i++) {       // zero W fp32 (64 x 64)
            int e = t + 512 * i;
            *(float*)(smem + F_WF + (e >> 6) * 272 + (e & 63) * 4) = 0.f;
        }
        // prefetch next pair (full pair latency to land)
        int np = pair + AO_GRID;
        if (np < NPAIR) {
            const float4* ks = (const float4*)(g_k
                + ((size_t)((np / PP) * TT + 32 + (np % PP)) * VV) * DD);
            const float4* qs = (const float4*)(g_q + (size_t)np * VV * DD);
#pragma unroll
            for (int i = 0; i < 4; i++) { kp[i] = ks[t + 512 * i]; qp[i] = qs[t + 512 * i]; }
        }
        __syncthreads();                                   // (1)

        // ---- P1: S = q @ k^T ----
        {
            float acc[2][4];
#pragma unroll
            for (int a = 0; a < 2; a++)
#pragma unroll
                for (int c = 0; c < 4; c++) acc[a][c] = 0.f;
            mma_S(sbase + F_QS, sbase + F_KR, lane, warp_m, warp_n, acc);
#pragma unroll
            for (int s2 = 0; s2 < 2; s2++) {
                int col = warp_n * 16 + s2 * 8 + 2 * (lane & 3);
                float* d = acc[s2];
                *(float2*)(smem + F_S + orow * 272 + col * 4) = make_float2(d[0], d[1]);
                *(float2*)(smem + F_S + (orow + 8) * 272 + col * 4) = make_float2(d[2], d[3]);
            }
        }
        __syncthreads();                                   // (2)

        // ---- P2: softmax gather + scatter into dense W ----
        {
            const int* cv = ccc + b * (VV * NN) + v * NN;
            int i0 = cv[to], i1 = cv[to + 8];
            const float* srow = (const float*)(smem + F_S + v * 272);
            float w0 = __expf(srow[i0] * scale);
            float w1 = __expf(srow[i1] * scale);
            float s = w0 + w1;
            s += __shfl_xor_sync(0xffffffffu, s, 1);
            s += __shfl_xor_sync(0xffffffffu, s, 2);
            s += __shfl_xor_sync(0xffffffffu, s, 4);
            float inv = 1.f / s;
            float* wrow = (float*)(smem + F_WF + v * 272);
            atomicAdd(wrow + i0, w0 * inv);
            atomicAdd(wrow + i1, w1 * inv);
        }
        __syncthreads();                                   // (3)

        // ---- P3: convert W fp32 -> split bf16 (64 x 64, 144B stride) ----
#pragma unroll
        for (int i = 0; i < 4; i++) {
            int e = t + 512 * i;
            int r = e >> 5, p2 = e & 31;
            float2 pw = *(const float2*)(smem + F_WF + r * 272 + p2 * 8);
            uint32_t h, l;
            split2(pw.x, pw.y, h, l);
            *(uint32_t*)(smem + F_WS + r * 144 + p2 * 4) = h;
            *(uint32_t*)(smem + F_WS + 9216 + r * 144 + p2 * 4) = l;
        }
        __syncthreads();                                   // (4)

        // ---- P4: O = W @ k -> convert into O stage (aliases F_QS) ----
        {
            float acc[4][4];
#pragma unroll
            for (int a = 0; a < 4; a++)
#pragma unroll
                for (int c = 0; c < 4; c++) acc[a][c] = 0.f;
            mma_O(sbase + F_WS, sbase + F_KR, lane, warp_m, warp_n, acc);
#pragma unroll
            for (int nf = 0; nf < 4; nf++) {
                int col = ocol0 + nf * 8;
                float* d = acc[nf];
                uint32_t h, l;
                split2(d[0], d[1], h, l);
                char* p0 = smem + F_QS + orow * 272 + col * 2;
                *(uint32_t*)p0 = h;
                *(uint32_t*)(p0 + 17408) = l;
                split2(d[2], d[3], h, l);
                char* p1 = smem + F_QS + (orow + 8) * 272 + col * 2;
                *(uint32_t*)p1 = h;
                *(uint32_t*)(p1 + 17408) = l;
            }
        }
        __syncthreads();                                   // (5)

        // ---- P5: out = O @ Wout^T + bout ----
        {
            float acc[4][4];
#pragma unroll
            for (int a = 0; a < 4; a++)
#pragma unroll
                for (int c = 0; c < 4; c++) acc[a][c] = 0.f;
            mma_tile(sbase + F_QS, 17408, sbase + F_WO, lane, warp_m, warp_n, acc);
            size_t ob = (size_t)b * 8192 + (size_t)(32 + pair % PP) * 64;
#pragma unroll
            for (int nf = 0; nf < 4; nf++) {
                int col = ocol0 + nf * 8;
                float* d = acc[nf];
                *(float2*)(out + (ob + orow) * DD + col) =
                    make_float2(d[0] + bv[nf].x, d[1] + bv[nf].y);
                *(float2*)(out + (ob + orow + 8) * DD + col) =
                    make_float2(d[2] + bv[nf].x, d[3] + bv[nf].y);
            }
        }
        __syncthreads();                                   // (6)
    }

    // ---- tail: out rows t<32 from g_kb (2 x 32-row tiles per chunk) ----
    int g2 = wid >> 3, w7 = wid & 7;
    int warp_m2 = w7 >> 2;
    int orow2 = warp_m2 * 16 + (lane >> 2);

    for (int ch = blockIdx.x; ch < NCHUNK; ch += AO_GRID) {
        int m0a = ((2 * ch) >> 6) * 8192 + ((2 * ch) & 63) * 32;
        int m0b = ((2 * ch + 1) >> 6) * 8192 + ((2 * ch + 1) & 63) * 32;
#pragma unroll
        for (int k = 0; k < 4; k++) {
            int c = t + 512 * k;
            int g = c >> 10, cc = c & 1023;
            int hl = cc >> 9, cd = cc & 511;
            int row = cd >> 4, off = cd & 15;
            int m0 = g ? m0b : m0a;
            const uint32_t* src = (hl ? g_kbl : g_kbh) + (size_t)(m0 + row) * 64 + off * 4;
            uint32_t d = sbase + F_QS + g * 8704 + hl * 17408 + row * 272 + off * 16;
            CP_ASYNC16(d, src);
        }
        CP_COMMIT();
        CP_WAIT0();
        __syncthreads();

        float acc[4][4];
#pragma unroll
        for (int a = 0; a < 4; a++)
#pragma unroll
            for (int c = 0; c < 4; c++) acc[a][c] = 0.f;
        mma_tile(sbase + F_QS + g2 * 8704, 17408, sbase + F_WO,
                 lane, warp_m2, warp_n, acc);

        int m0 = g2 ? m0b : m0a;
#pragma unroll
        for (int nf = 0; nf < 4; nf++) {
            int col = ocol0 + nf * 8;
            float* d = acc[nf];
            size_t r0 = (size_t)(m0 + orow2);
            *(float2*)(out + r0 * DD + col) =
                make_float2(d[0] + bv[nf].x, d[1] + bv[nf].y);
            *(float2*)(out + (r0 + 8) * DD + col) =
                make_float2(d[2] + bv[nf].x, d[3] + bv[nf].y);
        }
        __syncthreads();
    }
}

// ---------------------------------------------------------------------------
extern "C" void kernel_launch(void* const* d_in, const int* in_sizes, int n_in,
                              void* d_out, int out_size) {
    const float* queries = (const float*)d_in[0];
    const float* keys    = (const float*)d_in[1];
    const int*   ccc     = (const int*)  d_in[2];
    const float* Wq      = (const float*)d_in[3];
    const float* bq      = (const float*)d_in[4];
    const float* Wkv     = (const float*)d_in[5];
    const float* bkv     = (const float*)d_in[6];
    const float* Wout    = (const float*)d_in[7];
    const float* bout    = (const float*)d_in[8];
    float* out = (float*)d_out;

    static bool attr_done = false;
    if (!attr_done) {
        cudaFuncSetAttribute(gemm_qk,  cudaFuncAttributeMaxDynamicSharedMemorySize, GEMM_SMEM);
        cudaFuncSetAttribute(attn_out, cudaFuncAttributeMaxDynamicSharedMemorySize, F_SMEM);
        attr_done = true;
    }

    gemm_qk<<<NCTA, 256, GEMM_SMEM>>>(queries, keys, Wq, Wkv, bq, bkv);
    attn_out<<<AO_GRID, 512, F_SMEM>>>(ccc, Wout, bout, out);
}